// round 16
// baseline (speedup 1.0000x reference)
#include <cuda_runtime.h>

#define T_ 512
#define K_ 8
#define D_ 8
#define CP_ 28

#define TT 4                 // t's per block (one per warp)
#define BT 256               // b's per block
#define NTHR 128
#define NPAIR 4              // 8 elements per thread as 4 f32x2 pairs
#define XPITCH (BT + 1)      // 257: bank-conflict-free pitch

typedef unsigned long long ull;

// ---------------- precomputed params ----------------
// q transposed + pair-duplicated: g_qT[((t*K + k)*D + j)*D + i] = (v,v), v = Q[i][j]*s[j]
__device__ ull        g_qT[T_ * K_ * D_ * D_];
__device__ ulonglong2 g_cn[T_ * K_ * D_];   // (.x = dup cq, .y = dup nc)
__device__ ull        g_w2[T_ * K_];        // dup softmax weight

__device__ __forceinline__ float ex2f(float x) {
    float r; asm("ex2.approx.ftz.f32 %0, %1;" : "=f"(r) : "f"(x)); return r;
}
__device__ __forceinline__ ull fma2(ull a, ull b, ull c) {
    ull d; asm("fma.rn.f32x2 %0, %1, %2, %3;" : "=l"(d) : "l"(a), "l"(b), "l"(c)); return d;
}
__device__ __forceinline__ ull mul2(ull a, ull b) {
    ull d; asm("mul.rn.f32x2 %0, %1, %2;" : "=l"(d) : "l"(a), "l"(b)); return d;
}
__device__ __forceinline__ ull pack2(float lo, float hi) {
    ull r; asm("mov.b64 %0, {%1, %2};" : "=l"(r) : "f"(lo), "f"(hi)); return r;
}
__device__ __forceinline__ void unpack2(ull v, float& lo, float& hi) {
    asm("mov.b64 {%0, %1}, %2;" : "=f"(lo), "=f"(hi) : "l"(v));
}

// ---------------- fused precompute: Cayley + scaling + centers + softmax ----------------
// 8 threads per (t,k); thread j owns column j of the Gauss-Jordan pair [N|P],
// N=I-A, P=I+A  ->  P becomes Q^T  (Q = (I-A)(I+A)^{-1}).  No pivoting needed.
__global__ void __launch_bounds__(256) prep_kernel(const float* __restrict__ cov,
                                                   const float* __restrict__ centers,
                                                   const float* __restrict__ wlog,
                                                   const float* __restrict__ lvar) {
    const unsigned FULL = 0xffffffffu;
    int gid = blockIdx.x * 32 + (threadIdx.x >> 3);   // matrix index (t*8+k), exact 4096
    int j   = threadIdx.x & 7;                        // owned column
    const float* v = cov + gid * CP_;

    float N[D_], P[D_];
#pragma unroll
    for (int i = 0; i < D_; i++) {
        float a = 0.f;
        if (i != j) {
            int lo = i < j ? i : j, hi = i < j ? j : i;
            int m = lo * 8 + hi;
            float val = (m < CP_) ? v[m] : v[55 - m];
            a = (j > i) ? -0.5f * val : 0.5f * val;
        }
        float d = (i == j) ? 1.f : 0.f;
        N[i] = d - a;
        P[i] = d + a;
    }

#pragma unroll
    for (int c = 0; c < D_; c++) {
        float ncc = __shfl_sync(FULL, N[c], c, 8);
        float piv = 1.0f / ncc;
        N[c] *= piv;  P[c] *= piv;
#pragma unroll
        for (int r = 0; r < D_; r++) {
            if (r == c) continue;
            float f = __shfl_sync(FULL, N[r], c, 8);   // N[r][c], held by lane c
            N[r] = fmaf(-f, N[c], N[r]);
            P[r] = fmaf(-f, P[c], P[r]);
        }
    }
    // thread j holds P[r] = Q^T[r][j] = Q[j][r]

    float lv     = fminf(fmaxf(lvar[gid * D_ + j], -3.5f), 3.5f);
    float s_own  = sqrtf(0.72134752044448169f * expf(-lv));   // sqrt(0.5*log2e/var)
    float nc_own = rsqrtf(6.283185307179586f * expf(lv));

    float s_all[D_];
#pragma unroll
    for (int r = 0; r < D_; r++) s_all[r] = __shfl_sync(FULL, s_own, r, 8);

    float ce = centers[gid * D_ + j];
    float qs[D_], part[D_];
#pragma unroll
    for (int r = 0; r < D_; r++) {
        qs[r]   = P[r] * s_all[r];      // q_scaled[i=j][col=r]
        part[r] = ce * qs[r];
    }
#pragma unroll
    for (int off = 1; off < 8; off <<= 1)
#pragma unroll
        for (int r = 0; r < D_; r++)
            part[r] += __shfl_xor_sync(FULL, part[r], off, 8);

    // transposed store: g_qT[gid][col=r][i=j] = qs[r]
#pragma unroll
    for (int r = 0; r < D_; r++)
        g_qT[gid * (D_ * D_) + r * D_ + j] = pack2(qs[r], qs[r]);

    g_cn[gid * D_ + j] = make_ulonglong2(pack2(-part[j], -part[j]),
                                         pack2(nc_own, nc_own));

    if (j == 0) {
        int t = gid >> 3;
        float num = expf(fminf(fmaxf(wlog[gid], -3.5f), 3.5f));
        float den = 0.f;
#pragma unroll
        for (int k = 0; k < K_; k++)
            den += expf(fminf(fmaxf(wlog[t * K_ + k], -3.5f), 3.5f));
        float w = num / den;
        g_w2[gid] = pack2(w, w);
    }
}

// ---------------- main evaluation ----------------
// Block = (TT=4 t's) x (BT=256 b's); warp w owns t = t0+w.
// x tile staged coalesced into s_x[t*8+d][b] (pitch 257, conflict-free transpose).
// p[b,t] = sum_k w_k * prod_d (nc_d * 2^{-y_d^2} + EPS)
#define SMEM_X   (TT * D_ * XPITCH * 4)                  // 32896 B (16B-aligned)
#define SMEM_Q   (TT * 256 * 16)                         // 16384 B
#define SMEM_CN  (TT * 64 * 16)                          // 4096 B
#define SMEM_W   (TT * K_ * 8)                           // 256 B
#define SMEM_SZ  (SMEM_X + SMEM_Q + SMEM_CN + SMEM_W)    // 53632 B

__global__ void __launch_bounds__(NTHR, 4) pdf_kernel(const float* __restrict__ x,
                                                      float* __restrict__ out, int B) {
    extern __shared__ char smem[];
    float*      s_x  = (float*)smem;                          // [TT*8][257]
    ulonglong2* s_q  = (ulonglong2*)(smem + SMEM_X);          // [TT][k*32+j*4+ii]
    ulonglong2* s_cn = (ulonglong2*)(smem + SMEM_X + SMEM_Q); // [TT][k*8+j]
    ull*        s_w  = (ull*)(smem + SMEM_X + SMEM_Q + SMEM_CN);

    const int t0  = blockIdx.y * TT;
    const int b0  = blockIdx.x * BT;
    const int tid = threadIdx.x;
    const int w   = tid >> 5;
    const int l   = tid & 31;
    const int valid = min(BT, B - b0);

    // ---- params for 4 t's -> shared (coalesced) ----
    {
        const ulonglong2* gq = reinterpret_cast<const ulonglong2*>(g_qT) + (size_t)t0 * 256;
#pragma unroll
        for (int i = 0; i < 8; i++) s_q[tid + i * NTHR] = gq[tid + i * NTHR];   // 1024
#pragma unroll
        for (int i = 0; i < 2; i++) s_cn[tid + i * NTHR] = g_cn[t0 * 64 + tid + i * NTHR];
        if (tid < TT * K_) s_w[tid] = g_w2[t0 * K_ + tid];
    }

    // ---- x tile -> shared, transposed to [t*8+d][b] ----
    // x[b][t0..t0+3][0..7] is 128B contiguous per b; flat float4 reads are coalesced.
#pragma unroll
    for (int i = 0; i < 16; i++) {
        int f  = tid + i * NTHR;       // float4 index 0..2047
        int bl = f >> 3;
        int q  = f & 7;
        int tl = q >> 1;
        int d0 = (q & 1) * 4;
        float4 v = make_float4(0.f, 0.f, 0.f, 0.f);
        if (bl < valid)
            v = *reinterpret_cast<const float4*>(
                    x + ((size_t)(b0 + bl) * T_ + (t0 + tl)) * D_ + d0);
        int row = tl * D_ + d0;
        s_x[(row + 0) * XPITCH + bl] = v.x;
        s_x[(row + 1) * XPITCH + bl] = v.y;
        s_x[(row + 2) * XPITCH + bl] = v.z;
        s_x[(row + 3) * XPITCH + bl] = v.w;
    }
    __syncthreads();

    // ---- fill x registers (conflict-free LDS, lane stride 4B) ----
    const float* xr = s_x + (w * D_) * XPITCH;
    ull xp[NPAIR][D_];
#pragma unroll
    for (int u = 0; u < NPAIR; u++) {
        int cl = l + u * 64;           // lo element, hi = cl+32
#pragma unroll
        for (int d = 0; d < D_; d++)
            xp[u][d] = pack2(xr[d * XPITCH + cl], xr[d * XPITCH + cl + 32]);
    }

    const ulonglong2* qbase  = s_q  + w * 256;
    const ulonglong2* cnbase = s_cn + w * 64;

    const ull EPS2 = 0x33D6BF9533D6BF95ull;   // (1e-7f, 1e-7f)
    ull p[NPAIR];
#pragma unroll
    for (int u = 0; u < NPAIR; u++) p[u] = 0ull;

#pragma unroll 1   // keep k-loop rolled: body fits L0 I-cache
    for (int k = 0; k < K_; k++) {
        const ulonglong2* qk  = qbase  + k * 32;
        const ulonglong2* cnk = cnbase + k * D_;
        ull prod[NPAIR];
#pragma unroll
        for (int j = 0; j < D_; j++) {
            ulonglong2 cn = cnk[j];
            ull y[NPAIR];
#pragma unroll
            for (int u = 0; u < NPAIR; u++) y[u] = cn.x;
#pragma unroll
            for (int ii = 0; ii < 4; ii++) {
                ulonglong2 q2 = qk[j * 4 + ii];      // dup pairs q[2ii][j], q[2ii+1][j]
#pragma unroll
                for (int u = 0; u < NPAIR; u++) y[u] = fma2(xp[u][2 * ii],     q2.x, y[u]);
#pragma unroll
                for (int u = 0; u < NPAIR; u++) y[u] = fma2(xp[u][2 * ii + 1], q2.y, y[u]);
            }
#pragma unroll
            for (int u = 0; u < NPAIR; u++) {
                ull z = mul2(y[u], y[u]);
                float zl, zh; unpack2(z, zl, zh);
                ull e = pack2(ex2f(-zl), ex2f(-zh));
                ull g = fma2(cn.y, e, EPS2);
                prod[u] = (j == 0) ? g : mul2(prod[u], g);
            }
        }
        ull wk = s_w[w * K_ + k];
#pragma unroll
        for (int u = 0; u < NPAIR; u++) p[u] = fma2(wk, prod[u], p[u]);
    }

    // ---- store out[b][t0+w] ----
    const int t = t0 + w;
#pragma unroll
    for (int u = 0; u < NPAIR; u++) {
        float rl, rh; unpack2(p[u], rl, rh);
        int il = l + u * 64, ih = il + 32;
        if (il < valid) out[(size_t)(b0 + il) * T_ + t] = rl;
        if (ih < valid) out[(size_t)(b0 + ih) * T_ + t] = rh;
    }
}

// ---------------- launch ----------------
extern "C" void kernel_launch(void* const* d_in, const int* in_sizes, int n_in,
                              void* d_out, int out_size) {
    const float* x       = (const float*)d_in[0];
    const float* centers = (const float*)d_in[1];
    const float* wl      = (const float*)d_in[2];
    const float* lv      = (const float*)d_in[3];
    const float* cov     = (const float*)d_in[4];
    float* out = (float*)d_out;

    int B = in_sizes[0] / (T_ * D_);

    cudaFuncSetAttribute(pdf_kernel, cudaFuncAttributeMaxDynamicSharedMemorySize, SMEM_SZ);

    prep_kernel<<<(T_ * K_ * 8) / 256, 256>>>(cov, centers, wl, lv);

    dim3 grid((B + BT - 1) / BT, T_ / TT);
    pdf_kernel<<<grid, NTHR, SMEM_SZ>>>(x, out, B);
}

// round 17
// speedup vs baseline: 1.4561x; 1.4561x over previous
#include <cuda_runtime.h>

#define T_ 512
#define K_ 8
#define D_ 8
#define CP_ 28

#define NTHR 128
#define NPAIR 2                    // ILP-4: 4 elements per thread as 2 f32x2 pairs
#define BTILE (NTHR * 2 * NPAIR)   // 512 b per block

typedef unsigned long long ull;

// ---------------- precomputed params ----------------
// q transposed + pair-duplicated: g_qT[((t*K + k)*D + j)*D + i] = (v,v), v = Q[i][j]*s[j]
__device__ ull        g_qT[T_ * K_ * D_ * D_];
__device__ ulonglong2 g_cn[T_ * K_ * D_];   // (.x = dup cq, .y = dup nc)
__device__ ull        g_w2[T_ * K_];        // dup softmax weight

__device__ __forceinline__ float ex2f(float x) {
    float r; asm("ex2.approx.ftz.f32 %0, %1;" : "=f"(r) : "f"(x)); return r;
}
__device__ __forceinline__ ull fma2(ull a, ull b, ull c) {
    ull d; asm("fma.rn.f32x2 %0, %1, %2, %3;" : "=l"(d) : "l"(a), "l"(b), "l"(c)); return d;
}
__device__ __forceinline__ ull mul2(ull a, ull b) {
    ull d; asm("mul.rn.f32x2 %0, %1, %2;" : "=l"(d) : "l"(a), "l"(b)); return d;
}
__device__ __forceinline__ ull pack2(float lo, float hi) {
    ull r; asm("mov.b64 %0, {%1, %2};" : "=l"(r) : "f"(lo), "f"(hi)); return r;
}
__device__ __forceinline__ void unpack2(ull v, float& lo, float& hi) {
    asm("mov.b64 {%0, %1}, %2;" : "=f"(lo), "=f"(hi) : "l"(v));
}

// ---------------- fused precompute: Cayley + scaling + centers + softmax ----------------
// 8 threads per (t,k); thread j owns column j of the Gauss-Jordan pair [N|P],
// N=I-A, P=I+A  ->  P becomes Q^T  (Q = (I-A)(I+A)^{-1}).  No pivoting needed.
__global__ void __launch_bounds__(256) prep_kernel(const float* __restrict__ cov,
                                                   const float* __restrict__ centers,
                                                   const float* __restrict__ wlog,
                                                   const float* __restrict__ lvar) {
    const unsigned FULL = 0xffffffffu;
    int gid = blockIdx.x * 32 + (threadIdx.x >> 3);   // matrix index (t*8+k), exact 4096
    int j   = threadIdx.x & 7;                        // owned column
    const float* v = cov + gid * CP_;

    float N[D_], P[D_];
#pragma unroll
    for (int i = 0; i < D_; i++) {
        float a = 0.f;
        if (i != j) {
            int lo = i < j ? i : j, hi = i < j ? j : i;
            int m = lo * 8 + hi;
            float val = (m < CP_) ? v[m] : v[55 - m];
            a = (j > i) ? -0.5f * val : 0.5f * val;
        }
        float d = (i == j) ? 1.f : 0.f;
        N[i] = d - a;
        P[i] = d + a;
    }

#pragma unroll
    for (int c = 0; c < D_; c++) {
        float ncc = __shfl_sync(FULL, N[c], c, 8);
        float piv = 1.0f / ncc;
        N[c] *= piv;  P[c] *= piv;
#pragma unroll
        for (int r = 0; r < D_; r++) {
            if (r == c) continue;
            float f = __shfl_sync(FULL, N[r], c, 8);   // N[r][c], held by lane c
            N[r] = fmaf(-f, N[c], N[r]);
            P[r] = fmaf(-f, P[c], P[r]);
        }
    }
    // thread j holds P[r] = Q^T[r][j] = Q[j][r]

    float lv     = fminf(fmaxf(lvar[gid * D_ + j], -3.5f), 3.5f);
    float s_own  = sqrtf(0.72134752044448169f * expf(-lv));   // sqrt(0.5*log2e/var)
    float nc_own = rsqrtf(6.283185307179586f * expf(lv));

    float s_all[D_];
#pragma unroll
    for (int r = 0; r < D_; r++) s_all[r] = __shfl_sync(FULL, s_own, r, 8);

    float ce = centers[gid * D_ + j];
    float qs[D_], part[D_];
#pragma unroll
    for (int r = 0; r < D_; r++) {
        qs[r]   = P[r] * s_all[r];      // q_scaled[i=j][col=r]
        part[r] = ce * qs[r];
    }
#pragma unroll
    for (int off = 1; off < 8; off <<= 1)
#pragma unroll
        for (int r = 0; r < D_; r++)
            part[r] += __shfl_xor_sync(FULL, part[r], off, 8);

    // transposed store: g_qT[gid][col=r][i=j] = qs[r]
#pragma unroll
    for (int r = 0; r < D_; r++)
        g_qT[gid * (D_ * D_) + r * D_ + j] = pack2(qs[r], qs[r]);

    g_cn[gid * D_ + j] = make_ulonglong2(pack2(-part[j], -part[j]),
                                         pack2(nc_own, nc_own));

    if (j == 0) {
        int t = gid >> 3;
        float num = expf(fminf(fmaxf(wlog[gid], -3.5f), 3.5f));
        float den = 0.f;
#pragma unroll
        for (int k = 0; k < K_; k++)
            den += expf(fminf(fmaxf(wlog[t * K_ + k], -3.5f), 3.5f));
        float w = num / den;
        g_w2[gid] = pack2(w, w);
    }
}

// ---------------- main evaluation ----------------
// p[b,t] = sum_k w_k * prod_d (nc_d * 2^{-y_d^2} + EPS)
// ILP-4 (2 f32x2 pairs), 128 threads, 8 CTAs/SM: occupancy-overlap configuration.
__global__ void __launch_bounds__(NTHR, 8) pdf_kernel(const float* __restrict__ x,
                                                      float* __restrict__ out, int B) {
    const int t   = blockIdx.y;
    const int tid = threadIdx.x;

    __shared__ ulonglong2 s_q [K_ * D_ * D_ / 2];  // [k*32 + j*4 + ii] : 4 KB
    __shared__ ulonglong2 s_cn[K_ * D_];           // 1 KB
    __shared__ ull        s_w [K_];

    {
        const ulonglong2* gq = reinterpret_cast<const ulonglong2*>(g_qT) + (size_t)t * 256;
        s_q[tid]       = gq[tid];
        s_q[tid + 128] = gq[tid + 128];
        if (tid < 64) s_cn[tid] = g_cn[t * 64 + tid];
        else if (tid < 72) s_w[tid - 64] = g_w2[t * K_ + (tid - 64)];
    }
    __syncthreads();

    const int b0 = blockIdx.x * BTILE + tid;

    // load x for 4 elements; pair u covers b = b0 + (2u)*NTHR and b0 + (2u+1)*NTHR
    ull xp[NPAIR][D_];
#pragma unroll
    for (int u = 0; u < NPAIR; u++) {
        float xl[D_], xh[D_];
        int bl = b0 + (2 * u) * NTHR, bh = bl + NTHR;
#pragma unroll
        for (int d = 0; d < D_; d++) { xl[d] = 0.f; xh[d] = 0.f; }
        if (bl < B) {
            const float4* xpt = reinterpret_cast<const float4*>(x) + ((size_t)bl * T_ + t) * 2;
            float4 lo = xpt[0], hi = xpt[1];
            xl[0]=lo.x; xl[1]=lo.y; xl[2]=lo.z; xl[3]=lo.w;
            xl[4]=hi.x; xl[5]=hi.y; xl[6]=hi.z; xl[7]=hi.w;
        }
        if (bh < B) {
            const float4* xpt = reinterpret_cast<const float4*>(x) + ((size_t)bh * T_ + t) * 2;
            float4 lo = xpt[0], hi = xpt[1];
            xh[0]=lo.x; xh[1]=lo.y; xh[2]=lo.z; xh[3]=lo.w;
            xh[4]=hi.x; xh[5]=hi.y; xh[6]=hi.z; xh[7]=hi.w;
        }
#pragma unroll
        for (int d = 0; d < D_; d++) xp[u][d] = pack2(xl[d], xh[d]);
    }

    const ull EPS2 = 0x33D6BF9533D6BF95ull;   // (1e-7f, 1e-7f)
    ull p[NPAIR];
#pragma unroll
    for (int u = 0; u < NPAIR; u++) p[u] = 0ull;

#pragma unroll 1   // keep k-loop rolled: body fits L0 I-cache
    for (int k = 0; k < K_; k++) {
        const ulonglong2* qk  = s_q  + k * 32;
        const ulonglong2* cnk = s_cn + k * D_;
        ull prod[NPAIR];
#pragma unroll
        for (int j = 0; j < D_; j++) {
            ulonglong2 cn = cnk[j];
            ull y[NPAIR];
#pragma unroll
            for (int u = 0; u < NPAIR; u++) y[u] = cn.x;
#pragma unroll
            for (int ii = 0; ii < 4; ii++) {
                ulonglong2 q2 = qk[j * 4 + ii];      // dup pairs q[2ii][j], q[2ii+1][j]
#pragma unroll
                for (int u = 0; u < NPAIR; u++) y[u] = fma2(xp[u][2 * ii],     q2.x, y[u]);
#pragma unroll
                for (int u = 0; u < NPAIR; u++) y[u] = fma2(xp[u][2 * ii + 1], q2.y, y[u]);
            }
#pragma unroll
            for (int u = 0; u < NPAIR; u++) {
                ull z = mul2(y[u], y[u]);
                float zl, zh; unpack2(z, zl, zh);
                ull e = pack2(ex2f(-zl), ex2f(-zh));
                ull g = fma2(cn.y, e, EPS2);
                prod[u] = (j == 0) ? g : mul2(prod[u], g);
            }
        }
        ull wk = s_w[k];
#pragma unroll
        for (int u = 0; u < NPAIR; u++) p[u] = fma2(wk, prod[u], p[u]);
    }

#pragma unroll
    for (int u = 0; u < NPAIR; u++) {
        float rl, rh; unpack2(p[u], rl, rh);
        int bl = b0 + (2 * u) * NTHR, bh = bl + NTHR;
        if (bl < B) out[(size_t)bl * T_ + t] = rl;
        if (bh < B) out[(size_t)bh * T_ + t] = rh;
    }
}

// ---------------- launch ----------------
extern "C" void kernel_launch(void* const* d_in, const int* in_sizes, int n_in,
                              void* d_out, int out_size) {
    const float* x       = (const float*)d_in[0];
    const float* centers = (const float*)d_in[1];
    const float* wl      = (const float*)d_in[2];
    const float* lv      = (const float*)d_in[3];
    const float* cov     = (const float*)d_in[4];
    float* out = (float*)d_out;

    int B = in_sizes[0] / (T_ * D_);

    prep_kernel<<<(T_ * K_ * 8) / 256, 256>>>(cov, centers, wl, lv);

    dim3 grid((B + BTILE - 1) / BTILE, T_);
    pdf_kernel<<<grid, NTHR>>>(x, out, B);
}